// round 14
// baseline (speedup 1.0000x reference)
#include <cuda_runtime.h>
#include <math.h>
#include <stdint.h>

// FocalCTCLoss: B=256, T=1024, V=128, L=64, S=129, blank=127.
// LINEAR-domain fp32 CTC DP with exact power-of-2 rescaling.
// R14: TWO independent chains per warp (elements e0,e1, same direction)
// interleaved in one instruction stream -> deterministic stall filling.
// cp.async triple-buffered smem staging (no register rings, no LDG->STS
// round trip), Z row-sums from the staged tile, no inter-warp barriers.
// CTA = 64 thr: warp0 = fwd(e0)+fwd(e1), warp1 = bwd(e0)+bwd(e1).
// Grid 128 (2 elements per CTA). Fused last-CTA mean.

#define B_ 256
#define T_ 1024
#define V_ 128
#define L_ 64
#define EPS_ 1e-7f
#define NEG (-1e30f)
#define LN2_ 0.6931471805599453f

__device__ float g_focal[B_];
__device__ unsigned int g_count;   // zero-init at load; reset by last CTA

__device__ __forceinline__ float ex2(float x){float r;asm("ex2.approx.ftz.f32 %0,%1;":"=f"(r):"f"(x));return r;}
__device__ __forceinline__ float lg2(float x){float r;asm("lg2.approx.ftz.f32 %0,%1;":"=f"(r):"f"(x));return r;}
__device__ __forceinline__ void cpa16(uint32_t s, const void* g){
    asm volatile("cp.async.ca.shared.global [%0], [%1], 16;" :: "r"(s), "l"(g) : "memory");
}
#define CPCOMMIT() asm volatile("cp.async.commit_group;" ::: "memory")
#define CPWAIT2()  asm volatile("cp.async.wait_group 2;" ::: "memory")

__global__ void __launch_bounds__(64, 1) ctc_kernel(const int* __restrict__ y_true,
                                                    const float* __restrict__ y_pred,
                                                    float* __restrict__ out) {
    // dynamic smem: stile [wid][buf3][E2][row8][128f] = 12288 floats,
    //               szp   [wid][E2][16][33]           = 2112 floats
    extern __shared__ float dsm[];
    __shared__ float sbeta[2][132];
    __shared__ float szQ[2][2];      // [dir][elem] half-sums of lg2(Z)
    __shared__ float sfocal[2];
    __shared__ float sred[2];
    __shared__ unsigned int sIsLast;

    const int lane = threadIdx.x & 31;
    const int wid  = threadIdx.x >> 5;        // 0 = fwd, 1 = bwd
    const bool fwd = (wid == 0);
    const int b0 = (blockIdx.x << 1);

    const int dir = fwd ? 1 : -1;
    const int t0 = fwd ? 0 : 1023;
    const int edge = fwd ? 0 : 31;

    float* const stileW = dsm + wid * 6144;
    const uint32_t stW = (uint32_t)__cvta_generic_to_shared(stileW);
    float* const szpW = dsm + 12288 + wid * 1056;

    const char* const gm0 = (const char*)(y_pred + (size_t)b0 * (T_ * V_));
    const char* const gm1 = (const char*)(y_pred + (size_t)(b0 + 1) * (T_ * V_));

    // issue block c's cp.async for both elements (rows always in [0,1023]
    // for c <= 65: fwd t <= 527, bwd t >= 496)
#define ISSUE(c) {                                                            \
        const uint32_t dst = stW + ((c) % 3) * 8192 + (lane << 4);            \
        _Pragma("unroll")                                                     \
        for (int r = 0; r < 8; ++r) {                                         \
            const int tt = t0 + dir * ((c) * 8 + r);                          \
            cpa16(dst + r * 512,        gm0 + (size_t)tt * 512 + (lane << 4));\
            cpa16(dst + 4096 + r * 512, gm1 + (size_t)tt * 512 + (lane << 4));\
        }                                                                     \
        CPCOMMIT(); }

    ISSUE(0); ISSUE(1); ISSUE(2);   // start memory before anything else

    const int* lr0 = y_true + b0 * L_;
    const int* lr1 = y_true + (b0 + 1) * L_;
    const int lab1_0 = lr0[2 * lane], lab3_0 = lr0[2 * lane + 1];
    const int lab1_1 = lr1[2 * lane], lab3_1 = lr1[2 * lane + 1];
    const int labp0 = (lane > 0) ? lr0[2 * lane - 1] : 0;
    const int labp1 = (lane > 0) ? lr1[2 * lane - 1] : 0;
    const float sk1_0 = (lane > 0 && lab1_0 != labp0) ? 1.f : 0.f;
    const float sk3_0 = (lab3_0 != lab1_0) ? 1.f : 0.f;
    const float sk1_1 = (lane > 0 && lab1_1 != labp1) ? 1.f : 0.f;
    const float sk3_1 = (lab3_1 != lab1_1) ? 1.f : 0.f;

    float a0_0=0,a1_0=0,a2_0=0,a3_0=0,a4_0=0;
    float a0_1=0,a1_1=0,a2_1=0,a3_1=0,a4_1=0;
    int K_0 = 0, K_1 = 0;
    float sc_0 = (lane == edge) ? 0.f : 1.f, sc_1 = sc_0;
    float qB_0,q1_0,q3_0,qB_1,q1_1,q3_1;
    float pqB_0,pq1_0,pq3_0,pqB_1,pq1_1,pq3_1;
    float zp_0 = 0.f, zp_1 = 0.f;

    // per-step: Z row-partial (own float4) + 3 gathers, element E, row r of block c
#define QZ(E, r, c) {                                                         \
        const float* rw = tile##E + (r) * 128;                                \
        float4 z4 = *reinterpret_cast<const float4*>(rw + (lane << 2));       \
        szpW[(E) * 528 + ((((c) * 8 + (r)) & 15)) * 33 + lane] =              \
            (z4.x + z4.y) + (z4.z + z4.w);                                    \
        qB_##E = rw[127] + EPS_;                                              \
        q1_##E = rw[lab1_##E] + EPS_;                                         \
        q3_##E = rw[lab3_##E] + EPS_; }

#define TRANSZ(E) {                                                           \
        int rr = lane & 15; int j0 = (lane >> 4) << 4;                        \
        float Zs0 = 0.f, Zs1 = 0.f;                                           \
        _Pragma("unroll")                                                     \
        for (int j = 0; j < 16; j += 2) {                                     \
            Zs0 += szpW[(E) * 528 + rr * 33 + j0 + j];                        \
            Zs1 += szpW[(E) * 528 + rr * 33 + j0 + j + 1];                    \
        }                                                                     \
        float Zs = Zs0 + Zs1;                                                 \
        Zs += __shfl_down_sync(0xffffffffu, Zs, 16);                          \
        if (lane < 16) zp_##E += lg2(Zs + V_ * EPS_); }

#define RENORM_(E, SHV) {                                                     \
        float m = fmaxf(fmaxf(fmaxf(a0_##E, a1_##E), fmaxf(a2_##E, a3_##E)), a4_##E); \
        int ee = (int)(__float_as_uint(m) >> 23);                             \
        int ec = (ee > 0) ? ee : 127;                                         \
        K_##E += ec - 127;                                                    \
        float rsc = __int_as_float((unsigned)(254 - ec) << 23);               \
        a0_##E *= rsc; a1_##E *= rsc; a2_##E *= rsc; a3_##E *= rsc; a4_##E *= rsc; \
        int Kn = (SHV);                                                       \
        int d = Kn - K_##E; if (d > 127) d = 127;                             \
        sc_##E = (d < -126) ? 0.f : __int_as_float((unsigned)(d + 127) << 23);\
        if (lane == edge) sc_##E = 0.f; }

#define RENORM_F(E) RENORM_(E, __shfl_up_sync(0xffffffffu, K_##E, 1))
#define RENORM_B(E) RENORM_(E, __shfl_down_sync(0xffffffffu, K_##E, 1))

#define FWD_DP(E) {                                                           \
        float hi1 = __shfl_up_sync(0xffffffffu, a3_##E, 1) * sc_##E;          \
        float n0 = (a0_##E + hi1) * qB_##E;                                   \
        float n1 = fmaf(sk1_##E, hi1, a0_##E + a1_##E) * q1_##E;              \
        float n2 = (a1_##E + a2_##E) * qB_##E;                                \
        float n3 = fmaf(sk3_##E, a1_##E, a2_##E + a3_##E) * q3_##E;           \
        float n4 = (a3_##E + a4_##E) * qB_##E;                                \
        a0_##E = n0; a1_##E = n1; a2_##E = n2; a3_##E = n3;                   \
        a4_##E = (lane == 31) ? n4 : 0.f; }

#define BWD_DP(E) {                                                           \
        float c1v = a1_##E * pq1_##E;                                         \
        float c3v = a3_##E * pq3_##E;                                         \
        float cB2 = a2_##E * pqB_##E;                                         \
        float w = c1v * sk1_##E;                                              \
        float wd  = __shfl_down_sync(0xffffffffu, w, 1) * sc_##E;             \
        float b0d = __shfl_down_sync(0xffffffffu, a0_##E, 1) * sc_##E;        \
        float tt1 = (lane == 31) ? a4_##E : b0d;                              \
        float tt2 = (lane == 31) ? 0.f : wd;                                  \
        float n0 = fmaf(a0_##E, pqB_##E, c1v);                                \
        float n1 = fmaf(c3v, sk3_##E, c1v + cB2);                             \
        float n2 = cB2 + c3v;                                                 \
        float n3 = fmaf(tt1, pqB_##E, c3v + tt2);                             \
        float n4 = a4_##E * pqB_##E;                                          \
        a0_##E = n0; a1_##E = n1; a2_##E = n2; a3_##E = n3; a4_##E = n4;      \
        pqB_##E = qB_##E; pq1_##E = q1_##E; pq3_##E = q3_##E; }

    // ---- block 0 (row 0 = init) ----
    CPWAIT2(); __syncwarp();
    {
        const float* tile0 = stileW;
        const float* tile1 = stileW + 1024;
        if (fwd) {
            QZ(0, 0, 0); QZ(1, 0, 0);
            if (lane == 0) { a0_0 = qB_0; a1_0 = q1_0; a0_1 = qB_1; a1_1 = q1_1; }
#pragma unroll
            for (int r = 1; r < 8; ++r) { QZ(0, r, 0); QZ(1, r, 0); FWD_DP(0); FWD_DP(1); }
            RENORM_F(0); RENORM_F(1);
        } else {
            QZ(0, 0, 0); QZ(1, 0, 0);
            pqB_0 = qB_0; pq1_0 = q1_0; pq3_0 = q3_0;
            pqB_1 = qB_1; pq1_1 = q1_1; pq3_1 = q3_1;
            if (lane == 31) { a3_0 = 1.f; a4_0 = 1.f; a3_1 = 1.f; a4_1 = 1.f; }
#pragma unroll
            for (int r = 1; r < 8; ++r) { QZ(0, r, 0); QZ(1, r, 0); BWD_DP(0); BWD_DP(1); }
            RENORM_B(0); RENORM_B(1);
        }
    }
    ISSUE(3);

    // ---- blocks 1..63 ----
    for (int c = 1; c < 64; ++c) {
        CPWAIT2(); __syncwarp();
        const float* tile0 = stileW + (c % 3) * 2048;
        const float* tile1 = tile0 + 1024;
        if (fwd) {
#pragma unroll
            for (int r = 0; r < 8; ++r) { QZ(0, r, c); QZ(1, r, c); FWD_DP(0); FWD_DP(1); }
            RENORM_F(0); RENORM_F(1);
        } else {
#pragma unroll
            for (int r = 0; r < 8; ++r) { QZ(0, r, c); QZ(1, r, c); BWD_DP(0); BWD_DP(1); }
            RENORM_B(0); RENORM_B(1);
        }
        if (c & 1) { __syncwarp(); TRANSZ(0); TRANSZ(1); }
        if (c <= 62) ISSUE(c + 3);     // target buf (c%3) was consumed this block
    }

    // ---- per-direction Sum lg2(Z) (zp held in lanes < 16) ----
#pragma unroll
    for (int off = 16; off; off >>= 1) {
        zp_0 += __shfl_xor_sync(0xffffffffu, zp_0, off);
        zp_1 += __shfl_xor_sync(0xffffffffu, zp_1, off);
    }
    if (lane == 0) { szQ[wid][0] = zp_0; szQ[wid][1] = zp_1; }

    if (!fwd) {
#define STORE_BETA(E) {                                                       \
            float Kf = (float)K_##E;                                          \
            sbeta[E][4 * lane + 0] = lg2(a0_##E) + Kf;                        \
            sbeta[E][4 * lane + 1] = lg2(a1_##E) + Kf;                        \
            sbeta[E][4 * lane + 2] = lg2(a2_##E) + Kf;                        \
            sbeta[E][4 * lane + 3] = lg2(a3_##E) + Kf;                        \
            if (lane == 31) sbeta[E][128] = lg2(a4_##E) + Kf; }
        STORE_BETA(0); STORE_BETA(1);
    }
    __syncthreads();

    if (fwd) {
        // loglik = (LSE_s(log2 alpha'_511 + log2 beta'_511) - szTot) * ln2
#define FINAL(E) {                                                            \
            float Kf = (float)K_##E;                                          \
            float c0 = lg2(a0_##E) + Kf + sbeta[E][4 * lane + 0];             \
            float c1 = lg2(a1_##E) + Kf + sbeta[E][4 * lane + 1];             \
            float c2 = lg2(a2_##E) + Kf + sbeta[E][4 * lane + 2];             \
            float c3 = lg2(a3_##E) + Kf + sbeta[E][4 * lane + 3];             \
            float c4 = (lane == 31) ? (lg2(a4_##E) + Kf + sbeta[E][128]) : NEG; \
            float m = fmaxf(fmaxf(fmaxf(c0, c1), fmaxf(c2, c3)), c4);         \
            _Pragma("unroll")                                                 \
            for (int off = 16; off; off >>= 1)                                \
                m = fmaxf(m, __shfl_xor_sync(0xffffffffu, m, off));           \
            float s = ex2(c0 - m) + ex2(c1 - m) + ex2(c2 - m)                 \
                    + ex2(c3 - m) + ex2(c4 - m);                              \
            _Pragma("unroll")                                                 \
            for (int off = 16; off; off >>= 1)                                \
                s += __shfl_xor_sync(0xffffffffu, s, off);                    \
            if (lane == 0) {                                                  \
                float szTot = szQ[0][E] + szQ[1][E];                          \
                float loglik = (m + lg2(s) - szTot) * LN2_;                   \
                float loss = -loglik;                                         \
                float pp = expf(-loss);                                       \
                float om = 1.0f - pp;                                         \
                sfocal[E] = 0.25f * om * om * loss; } }
        FINAL(0); FINAL(1);
    }
    __syncthreads();

    // ---- fused mean: last CTA reduces all 256 focal values ----
    if (threadIdx.x == 0) {
        g_focal[b0] = sfocal[0];
        g_focal[b0 + 1] = sfocal[1];
        __threadfence();
        unsigned int old = atomicAdd(&g_count, 1u);
        sIsLast = (old == gridDim.x - 1) ? 1u : 0u;
    }
    __syncthreads();
    if (sIsLast) {
        float v = g_focal[threadIdx.x] + g_focal[threadIdx.x + 64]
                + g_focal[threadIdx.x + 128] + g_focal[threadIdx.x + 192];
#pragma unroll
        for (int off = 16; off; off >>= 1)
            v += __shfl_xor_sync(0xffffffffu, v, off);
        if (lane == 0) sred[wid] = v;
        __syncthreads();
        if (threadIdx.x == 0) {
            out[0] = (sred[0] + sred[1]) * (1.0f / (float)B_);
            g_count = 0;             // reset for next graph replay
        }
    }
}

extern "C" void kernel_launch(void* const* d_in, const int* in_sizes, int n_in,
                              void* d_out, int out_size) {
    const int* y_true;
    const float* y_pred;
    if (in_sizes[0] == B_ * L_) {
        y_true = (const int*)d_in[0];
        y_pred = (const float*)d_in[1];
    } else {
        y_true = (const int*)d_in[1];
        y_pred = (const float*)d_in[0];
    }
    const int smemBytes = (12288 + 2112) * 4;   // 57600 B dynamic
    cudaFuncSetAttribute(ctc_kernel, cudaFuncAttributeMaxDynamicSharedMemorySize, smemBytes);
    ctc_kernel<<<B_ / 2, 64, smemBytes>>>(y_true, y_pred, (float*)d_out);
}

// round 15
// speedup vs baseline: 1.1012x; 1.1012x over previous
#include <cuda_runtime.h>
#include <math.h>

// FocalCTCLoss: B=256, T=1024, V=128, L=64, S=129, blank=127.
// LINEAR-domain fp32 CTC DP with exact power-of-2 rescaling.
// R15: REGISTER-ONLY hot loop. Row lives in the warp's registers (LDG.128
// ring, depth 8); label gathers via SHFL.IDX (4 shfl + 2 sel per label),
// blank via 1 shfl from lane 31; Z via 8 batched fixed-point REDUX + lg2
// at block boundaries. NO smem, NO syncwarp, NO crossbar in the main loop.
// CTA = 128 thr: w0=fwd e0, w1=bwd e0, w2=fwd e1, w3=bwd e1. Grid 128.

#define B_ 256
#define T_ 1024
#define V_ 128
#define L_ 64
#define EPS_ 1e-7f
#define NEG (-1e30f)
#define LN2_ 0.6931471805599453f
#define FULL 0xffffffffu

__device__ float g_focal[B_];
__device__ unsigned int g_count;   // zero-init at load; reset by last CTA

__device__ __forceinline__ float ex2(float x){float r;asm("ex2.approx.ftz.f32 %0,%1;":"=f"(r):"f"(x));return r;}
__device__ __forceinline__ float lg2(float x){float r;asm("lg2.approx.ftz.f32 %0,%1;":"=f"(r):"f"(x));return r;}

__global__ void __launch_bounds__(128, 1) ctc_kernel(const int* __restrict__ y_true,
                                                     const float* __restrict__ y_pred,
                                                     float* __restrict__ out) {
    __shared__ float sbeta[2][132];  // bwd log2(beta') per state
    __shared__ float szH[4];         // per-warp Sum lg2(Z) halves
    __shared__ float sfocal[2];
    __shared__ float sred[4];
    __shared__ unsigned int sIsLast;

    const int lane = threadIdx.x & 31;
    const int wid = threadIdx.x >> 5;
    const bool fwd = ((wid & 1) == 0);
    const int e = wid >> 1;
    const int b = (blockIdx.x << 1) + e;

    const float4* yrow4 = reinterpret_cast<const float4*>(y_pred + (size_t)b * (T_ * V_));

    // Lane l owns states 4l..4l+3 (lane 31 also s=128).
    //  s=4l: blank  s=4l+1: label 2l  s=4l+2: blank  s=4l+3: label 2l+1
    const int* lr = y_true + b * L_;
    const int lab1 = lr[2 * lane];
    const int lab3 = lr[2 * lane + 1];
    const int labp = (lane > 0) ? lr[2 * lane - 1] : 0;
    const float sk1 = (lane > 0 && lab1 != labp) ? 1.0f : 0.0f;
    const float sk3 = (lab3 != lab1) ? 1.0f : 0.0f;
    const int s1 = lab1 >> 2, cs1 = lab1 & 3;    // shfl src lane / component
    const int s3 = lab3 >> 2, cs3 = lab3 & 3;

    const int dir = fwd ? 1 : -1;
    const int t0 = fwd ? 0 : 1023;
    const int edge = fwd ? 0 : 31;

    // LDG ring: yv[k] holds the float4 (components 4*lane..4*lane+3) of the
    // row for step i with i%8==k. Prefetch stays in [0,1023]: i+8 <= 519.
    float4 yv[8];
#pragma unroll
    for (int k = 0; k < 8; ++k) yv[k] = yrow4[(t0 + dir * k) * 32 + lane];

    float a0 = 0.f, a1 = 0.f, a2 = 0.f, a3 = 0.f, a4 = 0.f;
    int K = 0;
    float sc = (lane == edge) ? 0.0f : 1.0f;
    float qB, q1, q3, pqB, pq1, pq3;
    float zAcc = 0.f;
    float zp[8];

    // warp-register gather: value y[4*src+comp] -> all lanes (per-lane src/comp)
#define GATHER(y, src, comp, outv) {                                          \
        float vx = __shfl_sync(FULL, (y).x, (src));                           \
        float vy = __shfl_sync(FULL, (y).y, (src));                           \
        float vz = __shfl_sync(FULL, (y).z, (src));                           \
        float vw = __shfl_sync(FULL, (y).w, (src));                           \
        float v01 = ((comp) & 1) ? vy : vx;                                   \
        float v23 = ((comp) & 1) ? vw : vz;                                   \
        outv = (((comp) & 2) ? v23 : v01) + EPS_; }

    // STEP body for step i, ring slot k (literal): gathers + Z partial + refill
#define CONSUME(i, k) {                                                       \
        float4 y = yv[k];                                                     \
        yv[k] = yrow4[(t0 + dir * ((i) + 8)) * 32 + lane];                    \
        zp[k] = (y.x + y.y) + (y.z + y.w);                                    \
        qB = __shfl_sync(FULL, y.w, 31) + EPS_;                               \
        GATHER(y, s1, cs1, q1);                                               \
        GATHER(y, s3, cs3, q3); }

#define RENORM(SHFL_EXPR) {                                                   \
        float m = fmaxf(fmaxf(fmaxf(a0, a1), fmaxf(a2, a3)), a4);             \
        int ee = (int)(__float_as_uint(m) >> 23);                             \
        int ec = (ee > 0) ? ee : 127;                                         \
        K += ec - 127;                                                        \
        float rsc = __int_as_float((unsigned)(254 - ec) << 23);               \
        a0 *= rsc; a1 *= rsc; a2 *= rsc; a3 *= rsc; a4 *= rsc;                \
        int Kn = SHFL_EXPR;                                                   \
        int d = Kn - K; if (d > 127) d = 127;                                 \
        sc = (d < -126) ? 0.0f : __int_as_float((unsigned)(d + 127) << 23);   \
        if (lane == edge) sc = 0.0f; }

    // batched Z reduction for the 8 rows of the finished block (independent
    // REDUXes + lg2: high ILP, fills the RENORM chain's shadow)
#define ZBATCH() {                                                            \
        _Pragma("unroll")                                                     \
        for (int k = 0; k < 8; ++k) {                                         \
            int zi = __reduce_add_sync(FULL,                                  \
                                       __float2int_rn(zp[k] * 4194304.0f));   \
            zAcc += lg2((float)zi * (1.0f / 4194304.0f) + (V_ * EPS_));       \
        } }

#define FWD_DP() {                                                            \
        float hi1 = __shfl_up_sync(FULL, a3, 1) * sc;                         \
        float n0 = (a0 + hi1) * qB;                                           \
        float n1 = fmaf(sk1, hi1, a0 + a1) * q1;                              \
        float n2 = (a1 + a2) * qB;                                            \
        float n3 = fmaf(sk3, a1, a2 + a3) * q3;                               \
        float n4 = (a3 + a4) * qB;                                            \
        a0 = n0; a1 = n1; a2 = n2; a3 = n3;                                   \
        a4 = (lane == 31) ? n4 : 0.0f; }

#define BWD_DP() {                                                            \
        float c1 = a1 * pq1;                                                  \
        float c3 = a3 * pq3;                                                  \
        float cB2 = a2 * pqB;                                                 \
        float w = c1 * sk1;                                                   \
        float wd = __shfl_down_sync(FULL, w, 1) * sc;                         \
        float b0d = __shfl_down_sync(FULL, a0, 1) * sc;                       \
        float t1 = (lane == 31) ? a4 : b0d;                                   \
        float t2 = (lane == 31) ? 0.0f : wd;                                  \
        float n0 = fmaf(a0, pqB, c1);                                         \
        float n1 = fmaf(c3, sk3, c1 + cB2);                                   \
        float n2 = cB2 + c3;                                                  \
        float n3 = fmaf(t1, pqB, c3 + t2);                                    \
        float n4 = a4 * pqB;                                                  \
        a0 = n0; a1 = n1; a2 = n2; a3 = n3; a4 = n4;                          \
        pqB = qB; pq1 = q1; pq3 = q3; }

#define SH_UP   __shfl_up_sync(FULL, K, 1)
#define SH_DN   __shfl_down_sync(FULL, K, 1)

    if (fwd) {
        {   // block 0: step 0 = init, steps 1..7 DP
            CONSUME(0, 0);
            if (lane == 0) { a0 = qB; a1 = q1; }            // alpha'_0
            CONSUME(1, 1); FWD_DP();
            CONSUME(2, 2); FWD_DP();
            CONSUME(3, 3); FWD_DP();
            CONSUME(4, 4); FWD_DP();
            CONSUME(5, 5); FWD_DP();
            CONSUME(6, 6); FWD_DP();
            CONSUME(7, 7); FWD_DP();
            RENORM(SH_UP); ZBATCH();
        }
        for (int c = 1; c < 64; ++c) {                      // blocks 1..63
            const int base = c * 8;
            CONSUME(base + 0, 0); FWD_DP();
            CONSUME(base + 1, 1); FWD_DP();
            CONSUME(base + 2, 2); FWD_DP();
            CONSUME(base + 3, 3); FWD_DP();
            CONSUME(base + 4, 4); FWD_DP();
            CONSUME(base + 5, 5); FWD_DP();
            CONSUME(base + 6, 6); FWD_DP();
            CONSUME(base + 7, 7); FWD_DP();
            RENORM(SH_UP); ZBATCH();
        }
    } else {
        {   // block 0: step 0 loads q(1023) into pq + init, steps 1..7 DP
            CONSUME(0, 0);
            pqB = qB; pq1 = q1; pq3 = q3;
            if (lane == 31) { a3 = 1.0f; a4 = 1.0f; }       // beta_1023
            CONSUME(1, 1); BWD_DP();
            CONSUME(2, 2); BWD_DP();
            CONSUME(3, 3); BWD_DP();
            CONSUME(4, 4); BWD_DP();
            CONSUME(5, 5); BWD_DP();
            CONSUME(6, 6); BWD_DP();
            CONSUME(7, 7); BWD_DP();
            RENORM(SH_DN); ZBATCH();
        }
        for (int c = 1; c < 64; ++c) {                      // blocks 1..63
            const int base = c * 8;
            CONSUME(base + 0, 0); BWD_DP();
            CONSUME(base + 1, 1); BWD_DP();
            CONSUME(base + 2, 2); BWD_DP();
            CONSUME(base + 3, 3); BWD_DP();
            CONSUME(base + 4, 4); BWD_DP();
            CONSUME(base + 5, 5); BWD_DP();
            CONSUME(base + 6, 6); BWD_DP();
            CONSUME(base + 7, 7); BWD_DP();
            RENORM(SH_DN); ZBATCH();
        }
        float Kf = (float)K;
        sbeta[e][4 * lane + 0] = lg2(a0) + Kf;
        sbeta[e][4 * lane + 1] = lg2(a1) + Kf;
        sbeta[e][4 * lane + 2] = lg2(a2) + Kf;
        sbeta[e][4 * lane + 3] = lg2(a3) + Kf;
        if (lane == 31) sbeta[e][128] = lg2(a4) + Kf;
    }

    if (lane == 0) szH[wid] = zAcc;   // zAcc identical across lanes (REDUX)
    __syncthreads();

    if (fwd) {
        // loglik = (LSE_s(log2 alpha'_511 + log2 beta'_511) - szTot) * ln2
        float Kf = (float)K;
        float c0 = lg2(a0) + Kf + sbeta[e][4 * lane + 0];
        float c1 = lg2(a1) + Kf + sbeta[e][4 * lane + 1];
        float c2 = lg2(a2) + Kf + sbeta[e][4 * lane + 2];
        float c3 = lg2(a3) + Kf + sbeta[e][4 * lane + 3];
        float c4 = (lane == 31) ? (lg2(a4) + Kf + sbeta[e][128]) : NEG;
        float m = fmaxf(fmaxf(fmaxf(c0, c1), fmaxf(c2, c3)), c4);
#pragma unroll
        for (int off = 16; off; off >>= 1)
            m = fmaxf(m, __shfl_xor_sync(FULL, m, off));
        float s = ex2(c0 - m) + ex2(c1 - m) + ex2(c2 - m) + ex2(c3 - m) + ex2(c4 - m);
#pragma unroll
        for (int off = 16; off; off >>= 1)
            s += __shfl_xor_sync(FULL, s, off);
        if (lane == 0) {
            float szTot = szH[wid] + szH[wid + 1];
            float loglik = (m + lg2(s) - szTot) * LN2_;
            float loss = -loglik;
            float p = expf(-loss);
            float om = 1.0f - p;
            sfocal[e] = 0.25f * om * om * loss;
        }
    }
    __syncthreads();

    // ---- fused mean: last CTA reduces all 256 focal values in parallel ----
    if (threadIdx.x == 0) {
        const int b0 = blockIdx.x << 1;
        g_focal[b0] = sfocal[0];
        g_focal[b0 + 1] = sfocal[1];
        __threadfence();
        unsigned int old = atomicAdd(&g_count, 1u);
        sIsLast = (old == gridDim.x - 1) ? 1u : 0u;
    }
    __syncthreads();
    if (sIsLast) {
        float v = g_focal[threadIdx.x] + g_focal[threadIdx.x + 128];
#pragma unroll
        for (int off = 16; off; off >>= 1)
            v += __shfl_xor_sync(FULL, v, off);
        if (lane == 0) sred[wid] = v;
        __syncthreads();
        if (threadIdx.x == 0) {
            out[0] = ((sred[0] + sred[1]) + (sred[2] + sred[3])) * (1.0f / (float)B_);
            g_count = 0;             // reset for next graph replay
        }
    }
}

extern "C" void kernel_launch(void* const* d_in, const int* in_sizes, int n_in,
                              void* d_out, int out_size) {
    const int* y_true;
    const float* y_pred;
    if (in_sizes[0] == B_ * L_) {
        y_true = (const int*)d_in[0];
        y_pred = (const float*)d_in[1];
    } else {
        y_true = (const int*)d_in[1];
        y_pred = (const float*)d_in[0];
    }
    ctc_kernel<<<B_ / 2, 128>>>(y_true, y_pred, (float*)d_out);
}

// round 16
// speedup vs baseline: 1.1230x; 1.0198x over previous
#include <cuda_runtime.h>
#include <math.h>

// FocalCTCLoss: B=256, T=1024, V=128, L=64, S=129, blank=127.
// LINEAR-domain fp32 CTC DP with exact power-of-2 rescaling (R11 warp code,
// unchanged). R16: 2 warps per SMSP — grid 64 x 256 thr, 8 self-sufficient
// DP warps per CTA (4 elements x {fwd,bwd}); co-resident warp fills the
// other's LDS/SHFL stall shadow (hardware version of R14's interleaving).
// Staging in dynamic smem (82KB). Fused last-CTA mean.

#define B_ 256
#define T_ 1024
#define V_ 128
#define L_ 64
#define EPS_ 1e-7f
#define NEG (-1e30f)
#define LN2_ 0.6931471805599453f

__device__ float g_focal[B_];
__device__ unsigned int g_count;   // zero-init at load; reset by last CTA

__device__ __forceinline__ float ex2(float x){float r;asm("ex2.approx.ftz.f32 %0,%1;":"=f"(r):"f"(x));return r;}
__device__ __forceinline__ float lg2(float x){float r;asm("lg2.approx.ftz.f32 %0,%1;":"=f"(r):"f"(x));return r;}

__global__ void __launch_bounds__(256, 1) ctc_kernel(const int* __restrict__ y_true,
                                                     const float* __restrict__ y_pred,
                                                     float* __restrict__ out) {
    // dynamic smem: stage [8 warps][2 buf][8 rows][128 f] = 16384 floats,
    //               szp   [8 warps][16][33]              =  4224 floats
    extern __shared__ float dsm[];
    __shared__ float sbeta[4][132];      // bwd log2(beta') per element
    __shared__ float szHalf[8];          // per-warp Sum lg2(Z) halves
    __shared__ float sfocal[4];
    __shared__ float sred[8];
    __shared__ unsigned int sIsLast;

    const int lane = threadIdx.x & 31;
    const int wid = threadIdx.x >> 5;
    const bool fwd = ((wid & 1) == 0);
    const int e = wid >> 1;                       // element slot 0..3
    const int b = (blockIdx.x << 2) + e;

    const float4* yrow4 = reinterpret_cast<const float4*>(y_pred + (size_t)b * (T_ * V_));

    // Lane l owns states 4l..4l+3 (lane 31 also s=128).
    //  s=4l: blank  s=4l+1: label 2l  s=4l+2: blank  s=4l+3: label 2l+1
    const int* lr = y_true + b * L_;
    const int lab1 = lr[2 * lane];
    const int lab3 = lr[2 * lane + 1];
    const int labp = (lane > 0) ? lr[2 * lane - 1] : 0;
    const float sk1 = (lane > 0 && lab1 != labp) ? 1.0f : 0.0f;
    const float sk3 = (lab3 != lab1) ? 1.0f : 0.0f;

    const int dir = fwd ? 1 : -1;
    const int t0 = fwd ? 0 : 1023;
    const int edge = fwd ? 0 : 31;

    float* const sstW = dsm + wid * 2048;             // 2 bufs x 1024 floats
    float* const szpW = dsm + 16384 + wid * 528;      // 16 x 33 floats

    float4 rv[8];                       // register row ring for next block
#pragma unroll
    for (int r = 0; r < 8; ++r) rv[r] = yrow4[(t0 + dir * r) * 32 + lane];

    float a0 = 0.f, a1 = 0.f, a2 = 0.f, a3 = 0.f, a4 = 0.f;
    int K = 0;
    float sc = (lane == edge) ? 0.0f : 1.0f;
    float qB, q1, q3, pqB, pq1, pq3;
    float zpart = 0.f;

#define STAGE8(c)                                                             \
    {                                                                         \
        float4* dst = reinterpret_cast<float4*>(sst);                         \
        _Pragma("unroll")                                                     \
        for (int r = 0; r < 8; ++r) {                                         \
            float4 y = rv[r];                                                 \
            dst[r * 32 + lane] = y;                                           \
            szpW[((((c) * 8 + r) & 15)) * 33 + lane] =                        \
                (y.x + y.y) + (y.z + y.w);                                    \
        }                                                                     \
        __syncwarp();                                                         \
    }

#define PREFETCH8(c)                                                          \
    {                                                                         \
        _Pragma("unroll")                                                     \
        for (int r = 0; r < 8; ++r)                                           \
            rv[r] = yrow4[(t0 + dir * (((c) + 1) * 8 + r)) * 32 + lane];      \
    }

#define TRANSPOSE_Z()                                                         \
    {                                                                         \
        int rr = lane & 15;                                                   \
        int j0 = (lane >> 4) << 4;                                            \
        float Zs0 = 0.f, Zs1 = 0.f;                                           \
        _Pragma("unroll")                                                     \
        for (int j = 0; j < 16; j += 2) {                                     \
            Zs0 += szpW[rr * 33 + j0 + j];                                    \
            Zs1 += szpW[rr * 33 + j0 + j + 1];                                \
        }                                                                     \
        float Zs = Zs0 + Zs1;                                                 \
        Zs += __shfl_down_sync(0xffffffffu, Zs, 16);                          \
        if (lane < 16) zpart += lg2(Zs + V_ * EPS_);                          \
        __syncwarp();                                                         \
    }

#define QLDS_TO(r, oB, o1, o3)                                                \
    {                                                                         \
        const float* rw = sst + (r) * 128;                                    \
        oB = rw[127] + EPS_; o1 = rw[lab1] + EPS_; o3 = rw[lab3] + EPS_;      \
    }

#define RENORM(SHFL_EXPR)                                                     \
    {                                                                         \
        float m = fmaxf(fmaxf(fmaxf(a0, a1), fmaxf(a2, a3)), a4);             \
        int ee = (int)(__float_as_uint(m) >> 23);                             \
        int ec = (ee > 0) ? ee : 127;                                         \
        K += ec - 127;                                                        \
        float rsc = __int_as_float((unsigned)(254 - ec) << 23);               \
        a0 *= rsc; a1 *= rsc; a2 *= rsc; a3 *= rsc; a4 *= rsc;                \
        int Kn = SHFL_EXPR;                                                   \
        int d = Kn - K; if (d > 127) d = 127;                                 \
        sc = (d < -126) ? 0.0f : __int_as_float((unsigned)(d + 127) << 23);   \
        if (lane == edge) sc = 0.0f;                                          \
    }

#define FWD_DP()                                                              \
    {                                                                         \
        float hi1 = __shfl_up_sync(0xffffffffu, a3, 1) * sc;                  \
        float n0 = (a0 + hi1) * qB;                                           \
        float n1 = fmaf(sk1, hi1, a0 + a1) * q1;                              \
        float n2 = (a1 + a2) * qB;                                            \
        float n3 = fmaf(sk3, a1, a2 + a3) * q3;                               \
        float n4 = (a3 + a4) * qB;                                            \
        a0 = n0; a1 = n1; a2 = n2; a3 = n3;                                   \
        a4 = (lane == 31) ? n4 : 0.0f;                                        \
    }

#define FWD_STEP_PIPE(rnext)                                                  \
    {                                                                         \
        float tB, t1, t3;                                                     \
        QLDS_TO(rnext, tB, t1, t3);                                           \
        FWD_DP();                                                             \
        qB = tB; q1 = t1; q3 = t3;                                            \
    }

#define BWD_DP()                                                              \
    {                                                                         \
        float c1 = a1 * pq1;                                                  \
        float c3 = a3 * pq3;                                                  \
        float cB2 = a2 * pqB;                                                 \
        float w = c1 * sk1;                                                   \
        float wd = __shfl_down_sync(0xffffffffu, w, 1) * sc;                  \
        float b0d = __shfl_down_sync(0xffffffffu, a0, 1) * sc;                \
        float t1 = (lane == 31) ? a4 : b0d;                                   \
        float t2 = (lane == 31) ? 0.0f : wd;                                  \
        float n0 = fmaf(a0, pqB, c1);                                         \
        float n1 = fmaf(c3, sk3, c1 + cB2);                                   \
        float n2 = cB2 + c3;                                                  \
        float n3 = fmaf(t1, pqB, c3 + t2);                                    \
        float n4 = a4 * pqB;                                                  \
        a0 = n0; a1 = n1; a2 = n2; a3 = n3; a4 = n4;                          \
        pqB = qB; pq1 = q1; pq3 = q3;                                         \
    }

#define SH_UP   __shfl_up_sync(0xffffffffu, K, 1)
#define SH_DN   __shfl_down_sync(0xffffffffu, K, 1)

#define FWD_BLOCK(c, PF)                                                      \
    {                                                                         \
        float* sst = sstW + ((c) & 1) * 1024;                                 \
        STAGE8(c);                                                            \
        if (PF) PREFETCH8(c);                                                 \
        QLDS_TO(0, qB, q1, q3);                                               \
        FWD_STEP_PIPE(1); FWD_STEP_PIPE(2); FWD_STEP_PIPE(3);                 \
        FWD_STEP_PIPE(4); FWD_STEP_PIPE(5); FWD_STEP_PIPE(6);                 \
        FWD_STEP_PIPE(7);                                                     \
        FWD_DP(); RENORM(SH_UP);                                              \
    }

#define BWD_BLOCK(c, PF)                                                      \
    {                                                                         \
        float* sst = sstW + ((c) & 1) * 1024;                                 \
        STAGE8(c);                                                            \
        if (PF) PREFETCH8(c);                                                 \
        QLDS_TO(0, qB, q1, q3); BWD_DP();                                     \
        QLDS_TO(1, qB, q1, q3); BWD_DP();                                     \
        QLDS_TO(2, qB, q1, q3); BWD_DP();                                     \
        QLDS_TO(3, qB, q1, q3); BWD_DP();                                     \
        QLDS_TO(4, qB, q1, q3); BWD_DP();                                     \
        QLDS_TO(5, qB, q1, q3); BWD_DP();                                     \
        QLDS_TO(6, qB, q1, q3); BWD_DP();                                     \
        QLDS_TO(7, qB, q1, q3); BWD_DP();                                     \
        RENORM(SH_DN);                                                        \
    }

    if (fwd) {
        {   // block 0: row 0 is init, rows 1..7 are DP steps 1..7
            float* sst = sstW;
            STAGE8(0);
            PREFETCH8(0);
            QLDS_TO(0, qB, q1, q3);
            if (lane == 0) { a0 = qB; a1 = q1; }            // alpha'_0
            QLDS_TO(1, qB, q1, q3);
            FWD_STEP_PIPE(2); FWD_STEP_PIPE(3); FWD_STEP_PIPE(4);
            FWD_STEP_PIPE(5); FWD_STEP_PIPE(6); FWD_STEP_PIPE(7);
            FWD_DP(); RENORM(SH_UP);
        }
        for (int cp = 0; cp < 31; ++cp) {                   // blocks 1..62
            const int c = 2 * cp + 1;
            FWD_BLOCK(c, true); TRANSPOSE_Z();
            FWD_BLOCK(c + 1, true);
        }
        FWD_BLOCK(63, false); TRANSPOSE_Z();
    } else {
        {   // block 0: row 0 loads q(1023) into pq + init, rows 1..7 DP
            float* sst = sstW;
            STAGE8(0);
            PREFETCH8(0);
            QLDS_TO(0, qB, q1, q3);
            pqB = qB; pq1 = q1; pq3 = q3;
            if (lane == 31) { a3 = 1.0f; a4 = 1.0f; }       // beta_1023
            QLDS_TO(1, qB, q1, q3); BWD_DP();
            QLDS_TO(2, qB, q1, q3); BWD_DP();
            QLDS_TO(3, qB, q1, q3); BWD_DP();
            QLDS_TO(4, qB, q1, q3); BWD_DP();
            QLDS_TO(5, qB, q1, q3); BWD_DP();
            QLDS_TO(6, qB, q1, q3); BWD_DP();
            QLDS_TO(7, qB, q1, q3); BWD_DP();
            RENORM(SH_DN);
        }
        for (int cp = 0; cp < 31; ++cp) {                   // blocks 1..62
            const int c = 2 * cp + 1;
            BWD_BLOCK(c, true); TRANSPOSE_Z();
            BWD_BLOCK(c + 1, true);
        }
        BWD_BLOCK(63, false); TRANSPOSE_Z();
    }

    // per-warp Sum lg2(Z) over its 512 timesteps (lanes >=16 hold 0)
#pragma unroll
    for (int off = 16; off; off >>= 1)
        zpart += __shfl_xor_sync(0xffffffffu, zpart, off);
    if (lane == 0) szHalf[wid] = zpart;

    if (!fwd) {
        float Kf = (float)K;
        sbeta[e][4 * lane + 0] = lg2(a0) + Kf;
        sbeta[e][4 * lane + 1] = lg2(a1) + Kf;
        sbeta[e][4 * lane + 2] = lg2(a2) + Kf;
        sbeta[e][4 * lane + 3] = lg2(a3) + Kf;
        if (lane == 31) sbeta[e][128] = lg2(a4) + Kf;
    }
    __syncthreads();

    if (fwd) {
        // loglik = (LSE_s(log2 alpha'_511 + log2 beta'_511) - szTot) * ln2
        float Kf = (float)K;
        float c0 = lg2(a0) + Kf + sbeta[e][4 * lane + 0];
        float c1 = lg2(a1) + Kf + sbeta[e][4 * lane + 1];
        float c2 = lg2(a2) + Kf + sbeta[e][4 * lane + 2];
        float c3 = lg2(a3) + Kf + sbeta[e][4 * lane + 3];
        float c4 = (lane == 31) ? (lg2(a4) + Kf + sbeta[e][128]) : NEG;
        float m = fmaxf(fmaxf(fmaxf(c0, c1), fmaxf(c2, c3)), c4);
#pragma unroll
        for (int off = 16; off; off >>= 1)
            m = fmaxf(m, __shfl_xor_sync(0xffffffffu, m, off));
        float s = ex2(c0 - m) + ex2(c1 - m) + ex2(c2 - m) + ex2(c3 - m) + ex2(c4 - m);
#pragma unroll
        for (int off = 16; off; off >>= 1)
            s += __shfl_xor_sync(0xffffffffu, s, off);
        if (lane == 0) {
            float szTot = szHalf[wid] + szHalf[wid + 1];
            float loglik = (m + lg2(s) - szTot) * LN2_;
            float loss = -loglik;
            float p = expf(-loss);
            float om = 1.0f - p;
            sfocal[e] = 0.25f * om * om * loss;
        }
    }
    __syncthreads();

    // ---- fused mean: last CTA reduces all 256 focal values in parallel ----
    if (threadIdx.x == 0) {
        const int b0 = blockIdx.x << 2;
        g_focal[b0 + 0] = sfocal[0];
        g_focal[b0 + 1] = sfocal[1];
        g_focal[b0 + 2] = sfocal[2];
        g_focal[b0 + 3] = sfocal[3];
        __threadfence();
        unsigned int old = atomicAdd(&g_count, 1u);
        sIsLast = (old == gridDim.x - 1) ? 1u : 0u;
    }
    __syncthreads();
    if (sIsLast) {
        float v = g_focal[threadIdx.x];        // 256 threads, 256 values
#pragma unroll
        for (int off = 16; off; off >>= 1)
            v += __shfl_xor_sync(0xffffffffu, v, off);
        if (lane == 0) sred[wid] = v;
        __syncthreads();
        if (threadIdx.x == 0) {
            float tot = ((sred[0] + sred[1]) + (sred[2] + sred[3]))
                      + ((sred[4] + sred[5]) + (sred[6] + sred[7]));
            out[0] = tot * (1.0f / (float)B_);
            g_count = 0;             // reset for next graph replay
        }
    }
}

extern "C" void kernel_launch(void* const* d_in, const int* in_sizes, int n_in,
                              void* d_out, int out_size) {
    const int* y_true;
    const float* y_pred;
    if (in_sizes[0] == B_ * L_) {
        y_true = (const int*)d_in[0];
        y_pred = (const float*)d_in[1];
    } else {
        y_true = (const int*)d_in[1];
        y_pred = (const float*)d_in[0];
    }
    const int smemBytes = (16384 + 4224) * 4;   // 82432 B dynamic
    cudaFuncSetAttribute(ctc_kernel, cudaFuncAttributeMaxDynamicSharedMemorySize, smemBytes);
    ctc_kernel<<<B_ / 4, 256, smemBytes>>>(y_true, y_pred, (float*)d_out);
}

// round 17
// speedup vs baseline: 1.5195x; 1.3531x over previous
#include <cuda_runtime.h>
#include <math.h>
#include <stdint.h>

// FocalCTCLoss: B=256, T=1024, V=128, L=64, S=129, blank=127.
// LINEAR-domain fp32 CTC DP with exact power-of-2 rescaling.
// R17 (on R11-best): cp.async triple-buffered staging (no LDG ring / STS),
// q-gather LDS pipelined TWO steps ahead via 4-slot rotating register ring,
// Z via per-block register partials + batched fixed-point REDUX + lg2
// (no Z smem). Grid 128 x 128: w0=fwd e0, w1=bwd e0, w2=fwd e1, w3=bwd e1.

#define B_ 256
#define T_ 1024
#define V_ 128
#define L_ 64
#define EPS_ 1e-7f
#define NEG (-1e30f)
#define LN2_ 0.6931471805599453f
#define FULL 0xffffffffu

__device__ float g_focal[B_];
__device__ unsigned int g_count;   // zero-init at load; reset by last CTA

__device__ __forceinline__ float ex2(float x){float r;asm("ex2.approx.ftz.f32 %0,%1;":"=f"(r):"f"(x));return r;}
__device__ __forceinline__ float lg2(float x){float r;asm("lg2.approx.ftz.f32 %0,%1;":"=f"(r):"f"(x));return r;}
__device__ __forceinline__ void cpa16(uint32_t s, const void* g){
    asm volatile("cp.async.ca.shared.global [%0], [%1], 16;" :: "r"(s), "l"(g) : "memory");
}
#define CPCOMMIT() asm volatile("cp.async.commit_group;" ::: "memory")
#define CPWAIT1()  asm volatile("cp.async.wait_group 1;" ::: "memory")
#define CPWAIT0()  asm volatile("cp.async.wait_group 0;" ::: "memory")

__global__ void __launch_bounds__(128, 1) ctc_kernel(const int* __restrict__ y_true,
                                                     const float* __restrict__ y_pred,
                                                     float* __restrict__ out) {
    extern __shared__ float dsm[];       // [4 warps][3 bufs][1024 floats]
    __shared__ float sbeta[2][132];      // bwd log2(beta') per element
    __shared__ float szHalf[4];          // per-warp Sum lg2(Z) halves
    __shared__ float sfocal[2];
    __shared__ float sred[4];
    __shared__ unsigned int sIsLast;

    const int lane = threadIdx.x & 31;
    const int wid = threadIdx.x >> 5;
    const bool fwd = ((wid & 1) == 0);
    const int e = wid >> 1;
    const int b = (blockIdx.x << 1) + e;

    const int dir = fwd ? 1 : -1;
    const int t0 = fwd ? 0 : 1023;
    const int edge = fwd ? 0 : 31;

    float* const tileW = dsm + wid * 3072;
    const uint32_t tileWs = (uint32_t)__cvta_generic_to_shared(tileW);
    const char* const gmb = (const char*)(y_pred + (size_t)b * (T_ * V_));

    // issue block c (8 rows x 512 B) into buf c%3; rows in [0,1023] for c<=63
#define ISSUE(c) {                                                            \
        const uint32_t dst = tileWs + ((c) % 3) * 4096 + (lane << 4);         \
        _Pragma("unroll")                                                     \
        for (int r = 0; r < 8; ++r) {                                         \
            const int tt = t0 + dir * ((c) * 8 + r);                          \
            cpa16(dst + r * 512, gmb + (size_t)tt * 512 + (lane << 4));       \
        }                                                                     \
        CPCOMMIT(); }

    ISSUE(0); ISSUE(1); ISSUE(2);     // memory first

    // Lane l owns states 4l..4l+3 (lane 31 also s=128).
    const int* lr = y_true + b * L_;
    const int lab1 = lr[2 * lane];
    const int lab3 = lr[2 * lane + 1];
    const int labp = (lane > 0) ? lr[2 * lane - 1] : 0;
    const float sk1 = (lane > 0 && lab1 != labp) ? 1.0f : 0.0f;
    const float sk3 = (lab3 != lab1) ? 1.0f : 0.0f;

    float a0 = 0.f, a1 = 0.f, a2 = 0.f, a3 = 0.f, a4 = 0.f;
    int K = 0;
    float sc = (lane == edge) ? 0.0f : 1.0f;
    float zAcc = 0.f;
    float zp[8];
    // 4-slot rotating q-ring: slot S holds q(g) with g%4==S
    float pB0, pL0, pM0, pB1, pL1, pM1, pB2, pL2, pM2, pB3, pL3, pM3;

#define QLD(S, tile, r) {                                                     \
        const float* rw = (tile) + (r) * 128;                                 \
        pB##S = rw[127] + EPS_;                                               \
        pL##S = rw[lab1] + EPS_;                                              \
        pM##S = rw[lab3] + EPS_; }

#define ZREAD(tile, r) {                                                      \
        float4 zz = *reinterpret_cast<const float4*>((tile) + (r) * 128 + (lane << 2)); \
        zp[r] = (zz.x + zz.y) + (zz.z + zz.w); }

#define ZBATCH() {                                                            \
        _Pragma("unroll")                                                     \
        for (int k = 0; k < 8; ++k) {                                         \
            int zi = __reduce_add_sync(FULL,                                  \
                                       __float2int_rn(zp[k] * 4194304.0f));   \
            zAcc += lg2((float)zi * (1.0f / 4194304.0f) + (V_ * EPS_));       \
        } }

#define RENORM(SHFL_EXPR) {                                                   \
        float m = fmaxf(fmaxf(fmaxf(a0, a1), fmaxf(a2, a3)), a4);             \
        int ee = (int)(__float_as_uint(m) >> 23);                             \
        int ec = (ee > 0) ? ee : 127;                                         \
        K += ec - 127;                                                        \
        float rsc = __int_as_float((unsigned)(254 - ec) << 23);               \
        a0 *= rsc; a1 *= rsc; a2 *= rsc; a3 *= rsc; a4 *= rsc;                \
        int Kn = SHFL_EXPR;                                                   \
        int d = Kn - K; if (d > 127) d = 127;                                 \
        sc = (d < -126) ? 0.0f : __int_as_float((unsigned)(d + 127) << 23);   \
        if (lane == edge) sc = 0.0f; }

#define FWD_DP(S) {                                                           \
        float hi1 = __shfl_up_sync(FULL, a3, 1) * sc;                         \
        float n0 = (a0 + hi1) * pB##S;                                        \
        float n1 = fmaf(sk1, hi1, a0 + a1) * pL##S;                           \
        float n2 = (a1 + a2) * pB##S;                                         \
        float n3 = fmaf(sk3, a1, a2 + a3) * pM##S;                            \
        float n4 = (a3 + a4) * pB##S;                                         \
        a0 = n0; a1 = n1; a2 = n2; a3 = n3;                                   \
        a4 = (lane == 31) ? n4 : 0.0f; }

#define BWD_DP(S) {                                                           \
        float c1 = a1 * pL##S;                                                \
        float c3 = a3 * pM##S;                                                \
        float cB2 = a2 * pB##S;                                               \
        float w = c1 * sk1;                                                   \
        float wd = __shfl_down_sync(FULL, w, 1) * sc;                         \
        float b0d = __shfl_down_sync(FULL, a0, 1) * sc;                       \
        float t1 = (lane == 31) ? a4 : b0d;                                   \
        float t2 = (lane == 31) ? 0.0f : wd;                                  \
        float n0 = fmaf(a0, pB##S, c1);                                       \
        float n1 = fmaf(c3, sk3, c1 + cB2);                                   \
        float n2 = cB2 + c3;                                                  \
        float n3 = fmaf(t1, pB##S, c3 + t2);                                  \
        float n4 = a4 * pB##S;                                                \
        a0 = n0; a1 = n1; a2 = n2; a3 = n3; a4 = n4; }

#define SH_UP   __shfl_up_sync(FULL, K, 1)
#define SH_DN   __shfl_down_sync(FULL, K, 1)

    // generic blocks: step r consumes slot r&3 (FWD) / (r-1)&3 (BWD),
    // prefetches q(step r+2) into slot (r+2)&3 (rows 6,7 -> next tile).
#define FSTEPS(tc, tn, R6T, R6R, R7T, R7R)                                    \
        ZREAD(tc, 0); QLD(2, tc, 2); FWD_DP(0);                               \
        ZREAD(tc, 1); QLD(3, tc, 3); FWD_DP(1);                               \
        ZREAD(tc, 2); QLD(0, tc, 4); FWD_DP(2);                               \
        ZREAD(tc, 3); QLD(1, tc, 5); FWD_DP(3);                               \
        ZREAD(tc, 4); QLD(2, tc, 6); FWD_DP(0);                               \
        ZREAD(tc, 5); QLD(3, tc, 7); FWD_DP(1);                               \
        ZREAD(tc, 6); QLD(0, R6T, R6R); FWD_DP(2);                            \
        ZREAD(tc, 7); QLD(1, R7T, R7R); FWD_DP(3);                            \
        RENORM(SH_UP); ZBATCH();

#define BSTEPS(tc, tn, R6T, R6R, R7T, R7R)                                    \
        ZREAD(tc, 0); QLD(2, tc, 2); BWD_DP(3);                               \
        ZREAD(tc, 1); QLD(3, tc, 3); BWD_DP(0);                               \
        ZREAD(tc, 2); QLD(0, tc, 4); BWD_DP(1);                               \
        ZREAD(tc, 3); QLD(1, tc, 5); BWD_DP(2);                               \
        ZREAD(tc, 4); QLD(2, tc, 6); BWD_DP(3);                               \
        ZREAD(tc, 5); QLD(3, tc, 7); BWD_DP(0);                               \
        ZREAD(tc, 6); QLD(0, R6T, R6R); BWD_DP(1);                            \
        ZREAD(tc, 7); QLD(1, R7T, R7R); BWD_DP(2);                            \
        RENORM(SH_DN); ZBATCH();

    CPWAIT1(); __syncwarp();          // blocks 0,1 staged
    QLD(0, tileW, 0); QLD(1, tileW, 1);

    if (fwd) {
        {   // block 0: step 0 = init (consumes slot 0), steps 1..7 DP
            const float* tc = tileW;
            const float* tn = tileW + 1024;
            ZREAD(tc, 0); QLD(2, tc, 2);
            if (lane == 0) { a0 = pB0; a1 = pL0; }          // alpha'_0
            ZREAD(tc, 1); QLD(3, tc, 3); FWD_DP(1);
            ZREAD(tc, 2); QLD(0, tc, 4); FWD_DP(2);
            ZREAD(tc, 3); QLD(1, tc, 5); FWD_DP(3);
            ZREAD(tc, 4); QLD(2, tc, 6); FWD_DP(0);
            ZREAD(tc, 5); QLD(3, tc, 7); FWD_DP(1);
            ZREAD(tc, 6); QLD(0, tn, 0); FWD_DP(2);
            ZREAD(tc, 7); QLD(1, tn, 1); FWD_DP(3);
            RENORM(SH_UP); ZBATCH();
        }
        ISSUE(3);
        for (int c = 1; c <= 61; ++c) {
            CPWAIT1(); __syncwarp();
            const float* tc = tileW + (c % 3) * 1024;
            const float* tn = tileW + ((c + 1) % 3) * 1024;
            FSTEPS(tc, tn, tn, 0, tn, 1);
            if (c <= 60) ISSUE(c + 3);
        }
        {   // block 62 (needs tile 63 -> full drain)
            CPWAIT0(); __syncwarp();
            const float* tc = tileW + (62 % 3) * 1024;
            const float* tn = tileW + (63 % 3) * 1024;
            FSTEPS(tc, tn, tn, 0, tn, 1);
        }
        {   // block 63: dummy prefetches (values never consumed)
            const float* tc = tileW + (63 % 3) * 1024;
            FSTEPS(tc, tc, tc, 7, tc, 7);
        }
    } else {
        {   // block 0: step 0 = init only, steps 1..7 DP (consume q(0)..q(6))
            const float* tc = tileW;
            const float* tn = tileW + 1024;
            ZREAD(tc, 0); QLD(2, tc, 2);
            if (lane == 31) { a3 = 1.0f; a4 = 1.0f; }       // beta_1023
            ZREAD(tc, 1); QLD(3, tc, 3); BWD_DP(0);
            ZREAD(tc, 2); QLD(0, tc, 4); BWD_DP(1);
            ZREAD(tc, 3); QLD(1, tc, 5); BWD_DP(2);
            ZREAD(tc, 4); QLD(2, tc, 6); BWD_DP(3);
            ZREAD(tc, 5); QLD(3, tc, 7); BWD_DP(0);
            ZREAD(tc, 6); QLD(0, tn, 0); BWD_DP(1);
            ZREAD(tc, 7); QLD(1, tn, 1); BWD_DP(2);
            RENORM(SH_DN); ZBATCH();
        }
        ISSUE(3);
        for (int c = 1; c <= 61; ++c) {
            CPWAIT1(); __syncwarp();
            const float* tc = tileW + (c % 3) * 1024;
            const float* tn = tileW + ((c + 1) % 3) * 1024;
            BSTEPS(tc, tn, tn, 0, tn, 1);
            if (c <= 60) ISSUE(c + 3);
        }
        {
            CPWAIT0(); __syncwarp();
            const float* tc = tileW + (62 % 3) * 1024;
            const float* tn = tileW + (63 % 3) * 1024;
            BSTEPS(tc, tn, tn, 0, tn, 1);
        }
        {
            const float* tc = tileW + (63 % 3) * 1024;
            BSTEPS(tc, tc, tc, 7, tc, 7);
        }
        float Kf = (float)K;
        sbeta[e][4 * lane + 0] = lg2(a0) + Kf;
        sbeta[e][4 * lane + 1] = lg2(a1) + Kf;
        sbeta[e][4 * lane + 2] = lg2(a2) + Kf;
        sbeta[e][4 * lane + 3] = lg2(a3) + Kf;
        if (lane == 31) sbeta[e][128] = lg2(a4) + Kf;
    }

    if (lane == 0) szHalf[wid] = zAcc;   // zAcc uniform across lanes (REDUX)
    __syncthreads();

    if (fwd) {
        // loglik = (LSE_s(log2 alpha'_511 + log2 beta'_511) - szTot) * ln2
        float Kf = (float)K;
        float c0 = lg2(a0) + Kf + sbeta[e][4 * lane + 0];
        float c1 = lg2(a1) + Kf + sbeta[e][4 * lane + 1];
        float c2 = lg2(a2) + Kf + sbeta[e][4 * lane + 2];
        float c3 = lg2(a3) + Kf + sbeta[e][4 * lane + 3];
        float c4 = (lane == 31) ? (lg2(a4) + Kf + sbeta[e][128]) : NEG;
        float m = fmaxf(fmaxf(fmaxf(c0, c1), fmaxf(c2, c3)), c4);
#pragma unroll
        for (int off = 16; off; off >>= 1)
            m = fmaxf(m, __shfl_xor_sync(FULL, m, off));
        float s = ex2(c0 - m) + ex2(c1 - m) + ex2(c2 - m) + ex2(c3 - m) + ex2(c4 - m);
#pragma unroll
        for (int off = 16; off; off >>= 1)
            s += __shfl_xor_sync(FULL, s, off);
        if (lane == 0) {
            float szTot = szHalf[wid] + szHalf[wid + 1];
            float loglik = (m + lg2(s) - szTot) * LN2_;
            float loss = -loglik;
            float p = expf(-loss);
            float om = 1.0f - p;
            sfocal[e] = 0.25f * om * om * loss;
        }
    }
    __syncthreads();

    // ---- fused mean: last CTA reduces all 256 focal values in parallel ----
    if (threadIdx.x == 0) {
        const int b0 = blockIdx.x << 1;
        g_focal[b0] = sfocal[0];
        g_focal[b0 + 1] = sfocal[1];
        __threadfence();
        unsigned int old = atomicAdd(&g_count, 1u);
        sIsLast = (old == gridDim.x - 1) ? 1u : 0u;
    }
    __syncthreads();
    if (sIsLast) {
        float v = g_focal[threadIdx.x] + g_focal[threadIdx.x + 128];
#pragma unroll
        for (int off = 16; off; off >>= 1)
            v += __shfl_xor_sync(FULL, v, off);
        if (lane == 0) sred[wid] = v;
        __syncthreads();
        if (threadIdx.x == 0) {
            out[0] = ((sred[0] + sred[1]) + (sred[2] + sred[3])) * (1.0f / (float)B_);
            g_count = 0;             // reset for next graph replay
        }
    }
}

extern "C" void kernel_launch(void* const* d_in, const int* in_sizes, int n_in,
                              void* d_out, int out_size) {
    const int* y_true;
    const float* y_pred;
    if (in_sizes[0] == B_ * L_) {
        y_true = (const int*)d_in[0];
        y_pred = (const float*)d_in[1];
    } else {
        y_true = (const int*)d_in[1];
        y_pred = (const float*)d_in[0];
    }
    const int smemBytes = 4 * 3072 * 4;   // 49152 B dynamic
    cudaFuncSetAttribute(ctc_kernel, cudaFuncAttributeMaxDynamicSharedMemorySize, smemBytes);
    ctc_kernel<<<B_ / 2, 128, smemBytes>>>(y_true, y_pred, (float*)d_out);
}